// round 1
// baseline (speedup 1.0000x reference)
#include <cuda_runtime.h>

// RBF_random: out[b][o] = (1-d)^6 * (35 d^2 + 18 d + 3)/3 * w[o],
//   d = ||x[b] - c[o]||_2,  B=131072, OUT=512, IN=3.
// Output-BW-bound (268 MB). Packed f32x2 math keeps the FMA pipe under the
// HBM floor; centers/weights live in registers (4 outputs per thread).

typedef unsigned long long u64;

#define ROWS_PER_BLOCK 32
#define THREADS 128           // OUT/4 = 512/4

__device__ __forceinline__ u64 pack2(float lo, float hi) {
    u64 r; asm("mov.b64 %0, {%1, %2};" : "=l"(r) : "f"(lo), "f"(hi)); return r;
}
__device__ __forceinline__ void unpack2(u64 v, float& lo, float& hi) {
    asm("mov.b64 {%0, %1}, %2;" : "=f"(lo), "=f"(hi) : "l"(v));
}
__device__ __forceinline__ u64 add2(u64 a, u64 b) {
    u64 d; asm("add.rn.f32x2 %0, %1, %2;" : "=l"(d) : "l"(a), "l"(b)); return d;
}
__device__ __forceinline__ u64 mul2(u64 a, u64 b) {
    u64 d; asm("mul.rn.f32x2 %0, %1, %2;" : "=l"(d) : "l"(a), "l"(b)); return d;
}
__device__ __forceinline__ u64 fma2(u64 a, u64 b, u64 c) {
    u64 d; asm("fma.rn.f32x2 %0, %1, %2, %3;" : "=l"(d) : "l"(a), "l"(b), "l"(c)); return d;
}
__device__ __forceinline__ float sqrt_ap(float x) {
    float r; asm("sqrt.approx.f32 %0, %1;" : "=f"(r) : "f"(x)); return r;
}

__global__ void __launch_bounds__(THREADS)
rbf_kernel(const float* __restrict__ x,
           const float* __restrict__ centers,
           const float* __restrict__ weights,
           float* __restrict__ out,
           int B)
{
    __shared__ float sx[ROWS_PER_BLOCK * 3];

    const int tid = threadIdx.x;
    const int o0  = tid * 4;   // 4 consecutive output columns per thread

    // Per-thread constants in registers: negated centers (so diff = add) and w/3.
    float cx[4], cy[4], cz[4], w[4];
#pragma unroll
    for (int i = 0; i < 4; i++) {
        cx[i] = -centers[(o0 + i) * 3 + 0];
        cy[i] = -centers[(o0 + i) * 3 + 1];
        cz[i] = -centers[(o0 + i) * 3 + 2];
        w[i]  = weights[o0 + i] * (1.0f / 3.0f);
    }
    const u64 ncx0 = pack2(cx[0], cx[1]), ncy0 = pack2(cy[0], cy[1]), ncz0 = pack2(cz[0], cz[1]);
    const u64 ncx1 = pack2(cx[2], cx[3]), ncy1 = pack2(cy[2], cy[3]), ncz1 = pack2(cz[2], cz[3]);
    const u64 w0   = pack2(w[0],  w[1]),  w1   = pack2(w[2],  w[3]);
    const u64 kone = pack2(1.0f, 1.0f);
    const u64 kneg = pack2(-1.0f, -1.0f);
    const u64 k18  = pack2(18.0f, 18.0f);
    const u64 k3   = pack2(3.0f, 3.0f);
    const u64 k35  = pack2(35.0f, 35.0f);

    const long b0 = (long)blockIdx.x * ROWS_PER_BLOCK;
    const int nrows = min(ROWS_PER_BLOCK, B - (int)b0);

    // Stage this block's x rows into smem (broadcast reads in the main loop).
    for (int i = tid; i < nrows * 3; i += THREADS)
        sx[i] = x[b0 * 3 + i];
    __syncthreads();

    for (int r = 0; r < nrows; r++) {
        const float xx = sx[r * 3 + 0];
        const float xy = sx[r * 3 + 1];
        const float xz = sx[r * 3 + 2];
        const u64 px = pack2(xx, xx), py = pack2(xy, xy), pz = pack2(xz, xz);

        u64 res0, res1;
        {   // outputs o0, o0+1
            u64 dx = add2(px, ncx0), dy = add2(py, ncy0), dz = add2(pz, ncz0);
            u64 d2 = mul2(dx, dx); d2 = fma2(dy, dy, d2); d2 = fma2(dz, dz, d2);
            float a, b_; unpack2(d2, a, b_);
            u64 d  = pack2(sqrt_ap(a), sqrt_ap(b_));
            u64 t  = fma2(d, kneg, kone);            // 1 - d
            u64 t2 = mul2(t, t), t4 = mul2(t2, t2), t6 = mul2(t4, t2);
            u64 p  = fma2(d, k18, k3); p = fma2(d2, k35, p);
            res0   = mul2(mul2(t6, p), w0);
        }
        {   // outputs o0+2, o0+3
            u64 dx = add2(px, ncx1), dy = add2(py, ncy1), dz = add2(pz, ncz1);
            u64 d2 = mul2(dx, dx); d2 = fma2(dy, dy, d2); d2 = fma2(dz, dz, d2);
            float a, b_; unpack2(d2, a, b_);
            u64 d  = pack2(sqrt_ap(a), sqrt_ap(b_));
            u64 t  = fma2(d, kneg, kone);
            u64 t2 = mul2(t, t), t4 = mul2(t2, t2), t6 = mul2(t4, t2);
            u64 p  = fma2(d, k18, k3); p = fma2(d2, k35, p);
            res1   = mul2(mul2(t6, p), w1);
        }

        float4 v;
        unpack2(res0, v.x, v.y);
        unpack2(res1, v.z, v.w);
        *reinterpret_cast<float4*>(out + (b0 + r) * 512 + o0) = v;  // STG.128, coalesced
    }
}

extern "C" void kernel_launch(void* const* d_in, const int* in_sizes, int n_in,
                              void* d_out, int out_size)
{
    const float* x       = (const float*)d_in[0];  // (B, 3)
    const float* centers = (const float*)d_in[1];  // (512, 3)
    const float* weights = (const float*)d_in[2];  // (512,)
    float* out           = (float*)d_out;          // (B, 512)

    const int B = in_sizes[0] / 3;
    const int grid = (B + ROWS_PER_BLOCK - 1) / ROWS_PER_BLOCK;
    rbf_kernel<<<grid, THREADS>>>(x, centers, weights, out, B);
}

// round 2
// speedup vs baseline: 1.3664x; 1.3664x over previous
#include <cuda_runtime.h>

// RBF_random: out[b][o] = (1-d)^6 * (35 d^2 + 18 d + 3)/3 * w[o],
//   d = ||x[b] - c[o]||,  B=131072, OUT=512, IN=3.
// Output-write-BW bound (268 MB). d^2 via dot-product form (per-thread -2c,
// |c|^2 in regs), w folded into polynomial coeffs, packed f32x2 math.

typedef unsigned long long u64;

#define ROWS    16
#define THREADS 128          // OUT/4 = 512/4

__device__ __forceinline__ u64 pack2(float lo, float hi) {
    u64 r; asm("mov.b64 %0, {%1, %2};" : "=l"(r) : "f"(lo), "f"(hi)); return r;
}
__device__ __forceinline__ void unpack2(u64 v, float& lo, float& hi) {
    asm("mov.b64 {%0, %1}, %2;" : "=f"(lo), "=f"(hi) : "l"(v));
}
__device__ __forceinline__ u64 add2(u64 a, u64 b) {
    u64 d; asm("add.rn.f32x2 %0, %1, %2;" : "=l"(d) : "l"(a), "l"(b)); return d;
}
__device__ __forceinline__ u64 mul2(u64 a, u64 b) {
    u64 d; asm("mul.rn.f32x2 %0, %1, %2;" : "=l"(d) : "l"(a), "l"(b)); return d;
}
__device__ __forceinline__ u64 fma2(u64 a, u64 b, u64 c) {
    u64 d; asm("fma.rn.f32x2 %0, %1, %2, %3;" : "=l"(d) : "l"(a), "l"(b), "l"(c)); return d;
}
__device__ __forceinline__ float sqrt_ap(float x) {
    float r; asm("sqrt.approx.f32 %0, %1;" : "=f"(r) : "f"(x)); return r;
}

__global__ void __launch_bounds__(THREADS, 8)
rbf_kernel(const float* __restrict__ x,
           const float* __restrict__ centers,
           const float* __restrict__ weights,
           float* __restrict__ out,
           int B)
{
    __shared__ float sx[ROWS * 3];

    const int tid = threadIdx.x;
    const int o0  = tid * 4;   // 4 consecutive output columns per thread

    // Per-thread constants: -2c, |c|^2, and w-folded polynomial coeffs.
    float m2x[4], m2y[4], m2z[4], c2[4], w35[4], w6[4], w1[4];
#pragma unroll
    for (int i = 0; i < 4; i++) {
        const float a = centers[(o0 + i) * 3 + 0];
        const float b = centers[(o0 + i) * 3 + 1];
        const float c = centers[(o0 + i) * 3 + 2];
        m2x[i] = -2.0f * a; m2y[i] = -2.0f * b; m2z[i] = -2.0f * c;
        c2[i]  = a * a + b * b + c * c;
        const float w = weights[o0 + i];
        w35[i] = w * (35.0f / 3.0f);
        w6[i]  = w * 6.0f;
        w1[i]  = w;
    }
    const u64 M2X0 = pack2(m2x[0], m2x[1]), M2X1 = pack2(m2x[2], m2x[3]);
    const u64 M2Y0 = pack2(m2y[0], m2y[1]), M2Y1 = pack2(m2y[2], m2y[3]);
    const u64 M2Z0 = pack2(m2z[0], m2z[1]), M2Z1 = pack2(m2z[2], m2z[3]);
    const u64 C20  = pack2(c2[0],  c2[1]),  C21  = pack2(c2[2],  c2[3]);
    const u64 P2W0 = pack2(w35[0], w35[1]), P2W1 = pack2(w35[2], w35[3]);
    const u64 P1W0 = pack2(w6[0],  w6[1]),  P1W1 = pack2(w6[2],  w6[3]);
    const u64 P0W0 = pack2(w1[0],  w1[1]),  P0W1 = pack2(w1[2],  w1[3]);
    const u64 KONE = pack2(1.0f, 1.0f);
    const u64 KNEG = pack2(-1.0f, -1.0f);

    const int b0 = blockIdx.x * ROWS;

    // Stage this block's x rows (ROWS*3 = 48 floats) into smem.
    if (tid < ROWS * 3) {
        int gi = b0 * 3 + tid;
        sx[tid] = (gi < B * 3) ? x[gi] : 0.0f;
    }
    __syncthreads();

    const int nrows = min(ROWS, B - b0);
    float* orow = out + (long)b0 * 512 + o0;

#pragma unroll 2
    for (int r = 0; r < nrows; r++) {
        const float xx = sx[r * 3 + 0];
        const float xy = sx[r * 3 + 1];
        const float xz = sx[r * 3 + 2];
        const float x2 = xx * xx + xy * xy + xz * xz;   // shared by all 4 outputs
        const u64 PX  = pack2(xx, xx), PY = pack2(xy, xy), PZ = pack2(xz, xz);
        const u64 PX2 = pack2(x2, x2);

        u64 res0, res1;
        {   // outputs o0, o0+1
            u64 d2 = fma2(M2Z0, PZ, add2(C20, PX2));
            d2 = fma2(M2Y0, PY, d2);
            d2 = fma2(M2X0, PX, d2);
            float a, b; unpack2(d2, a, b);
            u64 d  = pack2(sqrt_ap(fmaxf(a, 0.0f)), sqrt_ap(fmaxf(b, 0.0f)));
            u64 t  = fma2(d, KNEG, KONE);               // 1 - d
            u64 t2 = mul2(t, t), t3 = mul2(t2, t), t6 = mul2(t3, t3);
            u64 p  = fma2(d, P1W0, P0W0);
            p      = fma2(d2, P2W0, p);                 // (35w/3)d^2 + 6w d + w
            res0   = mul2(t6, p);
        }
        {   // outputs o0+2, o0+3
            u64 d2 = fma2(M2Z1, PZ, add2(C21, PX2));
            d2 = fma2(M2Y1, PY, d2);
            d2 = fma2(M2X1, PX, d2);
            float a, b; unpack2(d2, a, b);
            u64 d  = pack2(sqrt_ap(fmaxf(a, 0.0f)), sqrt_ap(fmaxf(b, 0.0f)));
            u64 t  = fma2(d, KNEG, KONE);
            u64 t2 = mul2(t, t), t3 = mul2(t2, t), t6 = mul2(t3, t3);
            u64 p  = fma2(d, P1W1, P0W1);
            p      = fma2(d2, P2W1, p);
            res1   = mul2(t6, p);
        }

        float4 v;
        unpack2(res0, v.x, v.y);
        unpack2(res1, v.z, v.w);
        *reinterpret_cast<float4*>(orow) = v;           // STG.128, warp-coalesced
        orow += 512;
    }
}

extern "C" void kernel_launch(void* const* d_in, const int* in_sizes, int n_in,
                              void* d_out, int out_size)
{
    const float* x       = (const float*)d_in[0];  // (B, 3)
    const float* centers = (const float*)d_in[1];  // (512, 3)
    const float* weights = (const float*)d_in[2];  // (512,)
    float* out           = (float*)d_out;          // (B, 512)

    const int B = in_sizes[0] / 3;
    const int grid = (B + ROWS - 1) / ROWS;
    rbf_kernel<<<grid, THREADS>>>(x, centers, weights, out, B);
}